// round 10
// baseline (speedup 1.0000x reference)
#include <cuda_runtime.h>
#include <float.h>
#include <cstdint>

#define QD 8192   // QUANT_DIM
#define ED 512    // EMBED_DIM
#define NT 8192   // N_TOKENS
#define CAP 256   // candidate capacity (overflow -> exact serial fallback)
#define GRID 444  // 3 blocks/SM x 148 SMs (68KB smem/block -> 3 resident)

// Scratch: weight.T [QD, ED] = 16 MB. Static __device__ global (no alloc).
__device__ float g_wT[(size_t)QD * ED];

// ---------------------------------------------------------------------------
// Kernel 1: tiled transpose weight[ED, QD] -> g_wT[QD, ED]
// ---------------------------------------------------------------------------
__global__ void transpose_kernel(const float* __restrict__ w) {
    __shared__ float tile[32][33];
    int qx = blockIdx.x * 32 + threadIdx.x;
    int ey = blockIdx.y * 32 + threadIdx.y;
#pragma unroll
    for (int j = 0; j < 32; j += 8)
        tile[threadIdx.y + j][threadIdx.x] = w[(size_t)(ey + j) * QD + qx];
    __syncthreads();
    int ex = blockIdx.y * 32 + threadIdx.x;
    int qy = blockIdx.x * 32 + threadIdx.y;
#pragma unroll
    for (int j = 0; j < 32; j += 8)
        g_wT[(size_t)(qy + j) * ED + ex] = tile[threadIdx.x][threadIdx.y + j];
}

// Strict total order lex(value desc, index asc) — matches jax.lax.top_k ties.
__device__ __forceinline__ bool lexgt(float av, int ai, float bv, int bi) {
    return (av > bv) || (av == bv && ai < bi);
}

__device__ __forceinline__ uint32_t smem_u32(const void* p) {
    uint32_t a;
    asm("{ .reg .u64 t; cvta.to.shared.u64 t, %1; cvt.u32.u64 %0, t; }"
        : "=r"(a) : "l"(p));
    return a;
}

__device__ __forceinline__ void bulk_copy_row(uint32_t dst, const float* src,
                                              uint32_t mbar) {
    asm volatile("mbarrier.arrive.expect_tx.shared.b64 _, [%0], %1;"
                 :: "r"(mbar), "r"((uint32_t)(QD * 4)) : "memory");
    asm volatile(
        "cp.async.bulk.shared::cluster.global.mbarrier::complete_tx::bytes "
        "[%0], [%1], %2, [%3];"
        :: "r"(dst), "l"(src), "r"((uint32_t)(QD * 4)), "r"(mbar) : "memory");
}

__device__ __forceinline__ void mbar_wait(uint32_t mbar, uint32_t parity) {
    uint32_t done;
    do {
        asm volatile(
            "{ .reg .pred p;\n\t"
            "mbarrier.try_wait.parity.acquire.cta.shared::cta.b64 p, [%1], %2, 0x989680;\n\t"
            "selp.b32 %0, 1, 0, p; }"
            : "=r"(done) : "r"(mbar), "r"(parity) : "memory");
    } while (!done);
}

// ---------------------------------------------------------------------------
// Kernel 2: persistent blocks, 2-stage double-buffered cp.async.bulk pipeline.
// While computing token i from buf[i&1], the fill for i+1 is in flight and
// the fill for i+2 issues as soon as buf[i&1] is drained -> DRAM never idles.
// ---------------------------------------------------------------------------
__global__ __launch_bounds__(256) void topk_gather_kernel(
    const float* __restrict__ x, float* __restrict__ out) {
    extern __shared__ __align__(128) float s_dyn[];   // 2 x QD floats (64 KB)
    float* const buf0 = s_dyn;
    float* const buf1 = s_dyn + QD;

    __shared__ float s_max[256];
    __shared__ float s_cv[CAP];
    __shared__ int   s_ci[CAP];
    __shared__ int   s_cnt;
    __shared__ float s_T8;
    __shared__ int   s_fin[8];
    __shared__ __align__(8) unsigned long long s_mbar[2];

    const int t = threadIdx.x;
    const uint32_t mb0 = smem_u32(&s_mbar[0]);
    const uint32_t mb1 = smem_u32(&s_mbar[1]);
    const uint32_t sb0 = smem_u32(buf0);
    const uint32_t sb1 = smem_u32(buf1);

    if (t == 0) {
        asm volatile("mbarrier.init.shared.b64 [%0], 1;" :: "r"(mb0) : "memory");
        asm volatile("mbarrier.init.shared.b64 [%0], 1;" :: "r"(mb1) : "memory");
    }
    __syncthreads();

    // Prologue: issue fills for this block's first two tokens.
    const int n0 = blockIdx.x;
    if (t == 0) {
        bulk_copy_row(sb0, x + (size_t)n0 * QD, mb0);
        int n1 = n0 + GRID;
        if (n1 < NT) bulk_copy_row(sb1, x + (size_t)n1 * QD, mb1);
    }

    int it = 0;
    for (int n = n0; n < NT; n += GRID, it++) {
        const int b = it & 1;
        const uint32_t mbar = b ? mb1 : mb0;
        const uint32_t sbuf = b ? sb1 : sb0;
        const float*   sptr = b ? buf1 : buf0;
        const uint32_t parity = (uint32_t)((it >> 1) & 1);

        mbar_wait(mbar, parity);
        if (t == 0) s_cnt = 0;

        // ---- Phase 1: per-thread max over 32 smem elems (LDS.128 + FMNMX).
        const float4* b4 = reinterpret_cast<const float4*>(sptr);
        float gmax[4];
#pragma unroll
        for (int c = 0; c < 4; c++) {
            float4 a = b4[(2 * c) * 256 + t];
            float4 bb = b4[(2 * c + 1) * 256 + t];
            float m0 = fmaxf(fmaxf(a.x, a.y), fmaxf(a.z, a.w));
            float m1 = fmaxf(fmaxf(bb.x, bb.y), fmaxf(bb.z, bb.w));
            gmax[c] = fmaxf(m0, m1);
        }
        float tmax = fmaxf(fmaxf(gmax[0], gmax[1]), fmaxf(gmax[2], gmax[3]));
        s_max[t] = tmax;
        __syncthreads();

        // ---- Phase 2 (warp 0): T8 = 8th-largest of the 256 thread maxima.
        // The 8 threads owning the top-8 maxima hold 8 distinct elements
        // >= T8, so every true top-8 element passes v >= T8.
        if (t < 32) {
            float m[8];
#pragma unroll
            for (int j = 0; j < 8; j++) m[j] = s_max[j * 32 + t];
#define VCE(i, j) { float lo = fminf(m[i], m[j]); m[i] = fmaxf(m[i], m[j]); m[j] = lo; }
            VCE(0, 1) VCE(2, 3) VCE(4, 5) VCE(6, 7)
            VCE(0, 2) VCE(1, 3) VCE(4, 6) VCE(5, 7)
            VCE(1, 2) VCE(5, 6)
            VCE(0, 4) VCE(1, 5) VCE(2, 6) VCE(3, 7)
            VCE(2, 4) VCE(3, 5)
            VCE(1, 2) VCE(3, 4) VCE(5, 6)
#undef VCE
#pragma unroll
            for (int s = 1; s < 32; s <<= 1) {
                float p[8];
#pragma unroll
                for (int r = 0; r < 8; r++) p[r] = __shfl_xor_sync(0xffffffffu, m[r], s);
                float L[8];
#pragma unroll
                for (int r = 0; r < 8; r++) L[r] = fmaxf(m[r], p[7 - r]);
#define VCE2(i, j) { float lo = fminf(L[i], L[j]); L[i] = fmaxf(L[i], L[j]); L[j] = lo; }
                VCE2(0, 4) VCE2(1, 5) VCE2(2, 6) VCE2(3, 7)
                VCE2(0, 2) VCE2(1, 3) VCE2(4, 6) VCE2(5, 7)
                VCE2(0, 1) VCE2(2, 3) VCE2(4, 5) VCE2(6, 7)
#undef VCE2
#pragma unroll
                for (int r = 0; r < 8; r++) m[r] = L[r];
            }
            if (t == 0) s_T8 = m[7];
        }
        __syncthreads();
        const float T8 = s_T8;

        // ---- Phase 3: rescan triggered groups from smem.
        if (tmax >= T8) {
#pragma unroll
            for (int c = 0; c < 4; c++) {
                if (gmax[c] >= T8) {
                    float4 a = b4[(2 * c) * 256 + t];
                    float4 bb = b4[(2 * c + 1) * 256 + t];
                    int ia = 4 * ((2 * c) * 256 + t);
                    int ib = 4 * ((2 * c + 1) * 256 + t);
                    float va[8] = {a.x, a.y, a.z, a.w, bb.x, bb.y, bb.z, bb.w};
                    int   id[8] = {ia, ia + 1, ia + 2, ia + 3,
                                   ib, ib + 1, ib + 2, ib + 3};
#pragma unroll
                    for (int j = 0; j < 8; j++) {
                        if (va[j] >= T8) {
                            int pos = atomicAdd(&s_cnt, 1);
                            if (pos < CAP) { s_cv[pos] = va[j]; s_ci[pos] = id[j]; }
                        }
                    }
                }
            }
        }
        __syncthreads();

        const int C = s_cnt;  // >= 8 guaranteed
        if (C <= CAP) {
            // ---- Phase 4 (warp 0): exact lex top-8 over candidates.
            if (t < 32) {
                float tv[8]; int ti[8];
#pragma unroll
                for (int r = 0; r < 8; r++) { tv[r] = -FLT_MAX; ti[r] = 0x7FFFFFFF; }
                for (int i = t; i < C; i += 32) {
                    float v = s_cv[i]; int id = s_ci[i];
                    if (lexgt(v, id, tv[7], ti[7])) {
                        tv[7] = v; ti[7] = id;
#pragma unroll
                        for (int p = 7; p > 0; p--) {
                            if (lexgt(tv[p], ti[p], tv[p - 1], ti[p - 1])) {
                                float fv = tv[p]; tv[p] = tv[p - 1]; tv[p - 1] = fv;
                                int   fi = ti[p]; ti[p] = ti[p - 1]; ti[p - 1] = fi;
                            }
                        }
                    }
                }
#pragma unroll
                for (int s = 1; s < 32; s <<= 1) {
                    float pv[8]; int pi[8];
#pragma unroll
                    for (int r = 0; r < 8; r++) {
                        pv[r] = __shfl_xor_sync(0xffffffffu, tv[r], s);
                        pi[r] = __shfl_xor_sync(0xffffffffu, ti[r], s);
                    }
                    float L[8]; int Li[8];
#pragma unroll
                    for (int r = 0; r < 8; r++) {
                        bool p = lexgt(tv[r], ti[r], pv[7 - r], pi[7 - r]);
                        L[r]  = p ? tv[r] : pv[7 - r];
                        Li[r] = p ? ti[r] : pi[7 - r];
                    }
#define LCE(i, j)                                                       \
                    {                                                   \
                        if (lexgt(L[j], Li[j], L[i], Li[i])) {          \
                            float fv = L[i]; L[i] = L[j]; L[j] = fv;    \
                            int   fi = Li[i]; Li[i] = Li[j]; Li[j] = fi;\
                        }                                               \
                    }
                    LCE(0, 4) LCE(1, 5) LCE(2, 6) LCE(3, 7)
                    LCE(0, 2) LCE(1, 3) LCE(4, 6) LCE(5, 7)
                    LCE(0, 1) LCE(2, 3) LCE(4, 5) LCE(6, 7)
#undef LCE
#pragma unroll
                    for (int r = 0; r < 8; r++) { tv[r] = L[r]; ti[r] = Li[r]; }
                }
                if (t < 8) s_fin[t] = ti[t];
            }
        } else {
            // Overflow fallback: exact serial scan (never on this data).
            if (t == 0) {
                float tv[8]; int ti[8];
#pragma unroll
                for (int r = 0; r < 8; r++) { tv[r] = -FLT_MAX; ti[r] = 0x7FFFFFFF; }
                for (int i = 0; i < QD; i++) {
                    float v = sptr[i];
                    if (lexgt(v, i, tv[7], ti[7])) {
                        tv[7] = v; ti[7] = i;
#pragma unroll
                        for (int p = 7; p > 0; p--) {
                            if (lexgt(tv[p], ti[p], tv[p - 1], ti[p - 1])) {
                                float fv = tv[p]; tv[p] = tv[p - 1]; tv[p - 1] = fv;
                                int   fi = ti[p]; ti[p] = ti[p - 1]; ti[p - 1] = fi;
                            }
                        }
                    }
                }
#pragma unroll
                for (int r = 0; r < 8; r++) s_fin[r] = ti[r];
            }
        }
        __syncthreads();

        // Buffer b fully drained: issue the fill for token n + 2*GRID NOW so
        // it overlaps this token's gather and the next token's compute.
        if (t == 0) {
            int nn = n + 2 * GRID;
            if (nn < NT) bulk_copy_row(sbuf, x + (size_t)nn * QD, mbar);
        }

        // ---- Phase 5: out[n, :] = sum_{j<8} wT[idx_j, :] (coalesced float2).
        // s_fin is value-descending == jax's summation order.
        int idx[8];
#pragma unroll
        for (int r = 0; r < 8; r++) idx[r] = s_fin[r];

        const float2* wT2 = reinterpret_cast<const float2*>(g_wT);
        float2 acc = make_float2(0.f, 0.f);
#pragma unroll
        for (int r = 0; r < 8; r++) {
            float2 w = wT2[(size_t)idx[r] * (ED / 2) + t];
            acc.x += w.x;
            acc.y += w.y;
        }
        reinterpret_cast<float2*>(out)[(size_t)n * (ED / 2) + t] = acc;

        // s_fin/s_cnt reuse is ordered by the Phase-1 __syncthreads of the
        // next iteration (all threads passed Phase-5 reads before any thread
        // rewrites them after that barrier).
        __syncthreads();
    }
}

// ---------------------------------------------------------------------------
extern "C" void kernel_launch(void* const* d_in, const int* in_sizes, int n_in,
                              void* d_out, int out_size) {
    const float* x = (const float*)d_in[0];   // [NT, QD] f32
    const float* w = (const float*)d_in[1];   // [ED, QD] f32
    float* out = (float*)d_out;               // [NT, ED] f32

    static int smem_set = 0;
    if (!smem_set) {
        cudaFuncSetAttribute(topk_gather_kernel,
                             cudaFuncAttributeMaxDynamicSharedMemorySize,
                             2 * QD * 4);
        smem_set = 1;
    }

    dim3 tb(32, 8);
    dim3 tg(QD / 32, ED / 32);
    transpose_kernel<<<tg, tb>>>(w);
    topk_gather_kernel<<<GRID, 256, 2 * QD * 4>>>(x, out);
}

// round 13
// speedup vs baseline: 1.0149x; 1.0149x over previous
#include <cuda_runtime.h>
#include <float.h>
#include <cstdint>

#define QD 8192   // QUANT_DIM
#define ED 512    // EMBED_DIM
#define NT 8192   // N_TOKENS
#define CAP 256   // candidate capacity (overflow -> exact serial fallback)

// Static scratch (no alloc): weight.T (16 MB), per-thread maxima (8 MB),
// selected indices (256 KB).
__device__ float g_wT[(size_t)QD * ED];
__device__ float g_gmax[(size_t)NT * 256];
__device__ int   g_idx[(size_t)NT * 8];

// ---------------------------------------------------------------------------
// Kernel A1: pure stream. Per-thread max over 32 strided elems of one token.
// No smem, no barriers, no tail -> block slots recycle into fresh streams.
// ---------------------------------------------------------------------------
__global__ __launch_bounds__(256) void rowmax_kernel(const float* __restrict__ x) {
    const int n = blockIdx.x;
    const int t = threadIdx.x;
    const float4* xr = reinterpret_cast<const float4*>(x + (size_t)n * QD);
    float4 v[8];
#pragma unroll
    for (int c = 0; c < 8; c++) v[c] = __ldcs(&xr[c * 256 + t]);
    float m = fmaxf(fmaxf(v[0].x, v[0].y), fmaxf(v[0].z, v[0].w));
#pragma unroll
    for (int c = 1; c < 8; c++)
        m = fmaxf(m, fmaxf(fmaxf(v[c].x, v[c].y), fmaxf(v[c].z, v[c].w)));
    g_gmax[(size_t)n * 256 + t] = m;
}

// Strict total order lex(value desc, index asc) — matches jax.lax.top_k ties.
__device__ __forceinline__ bool lexgt(float av, int ai, float bv, int bi) {
    return (av > bv) || (av == bv && ai < bi);
}

// ---------------------------------------------------------------------------
// Kernel A2: per-token top-8 index selection from the precomputed maxima.
// T8 = 8th-largest of the 256 thread maxima (redundant per-warp sort, no
// warp0 wait). The 8 threads owning the top-8 maxima hold 8 distinct
// elements >= T8, so every true top-8 element passes v >= T8.
// ---------------------------------------------------------------------------
__global__ __launch_bounds__(256) void select_kernel(const float* __restrict__ x) {
    const int n = blockIdx.x;
    const int t = threadIdx.x;
    const int lane = t & 31;

    __shared__ float s_max[256];
    __shared__ float s_cv[CAP];
    __shared__ int   s_ci[CAP];
    __shared__ int   s_cnt;

    const float mv = __ldg(&g_gmax[(size_t)n * 256 + t]);
    s_max[t] = mv;
    if (t == 0) s_cnt = 0;
    __syncthreads();

    // ---- T8: every warp redundantly sorts the 256 maxima (top-8 suffices).
    float m[8];
#pragma unroll
    for (int j = 0; j < 8; j++) m[j] = s_max[j * 32 + lane];
#define VCE(i, j) { float lo = fminf(m[i], m[j]); m[i] = fmaxf(m[i], m[j]); m[j] = lo; }
    VCE(0, 1) VCE(2, 3) VCE(4, 5) VCE(6, 7)
    VCE(0, 2) VCE(1, 3) VCE(4, 6) VCE(5, 7)
    VCE(1, 2) VCE(5, 6)
    VCE(0, 4) VCE(1, 5) VCE(2, 6) VCE(3, 7)
    VCE(2, 4) VCE(3, 5)
    VCE(1, 2) VCE(3, 4) VCE(5, 6)
#undef VCE
#pragma unroll
    for (int s = 1; s < 32; s <<= 1) {
        float p[8];
#pragma unroll
        for (int r = 0; r < 8; r++) p[r] = __shfl_xor_sync(0xffffffffu, m[r], s);
        float L[8];
#pragma unroll
        for (int r = 0; r < 8; r++) L[r] = fmaxf(m[r], p[7 - r]);
#define VCE2(i, j) { float lo = fminf(L[i], L[j]); L[i] = fmaxf(L[i], L[j]); L[j] = lo; }
        VCE2(0, 4) VCE2(1, 5) VCE2(2, 6) VCE2(3, 7)
        VCE2(0, 2) VCE2(1, 3) VCE2(4, 6) VCE2(5, 7)
        VCE2(0, 1) VCE2(2, 3) VCE2(4, 5) VCE2(6, 7)
#undef VCE2
#pragma unroll
        for (int r = 0; r < 8; r++) m[r] = L[r];
    }
    const float T8 = m[7];

    // ---- Rescan: triggered threads (~10/block) re-read their 32 elems.
    const float4* xr = reinterpret_cast<const float4*>(x + (size_t)n * QD);
    if (mv >= T8) {
#pragma unroll
        for (int c = 0; c < 8; c++) {
            float4 a = __ldg(&xr[c * 256 + t]);
            int base = 4 * (c * 256 + t);
            float va[4] = {a.x, a.y, a.z, a.w};
#pragma unroll
            for (int j = 0; j < 4; j++) {
                if (va[j] >= T8) {
                    int pos = atomicAdd(&s_cnt, 1);
                    if (pos < CAP) { s_cv[pos] = va[j]; s_ci[pos] = base + j; }
                }
            }
        }
    }
    __syncthreads();

    const int C = s_cnt;  // >= 8 guaranteed
    if (t >= 32) return;  // only warp 0 finishes; others free their slots

    if (C <= CAP) {
        // ---- Exact lex top-8 over the candidate list (warp 0).
        float tv[8]; int ti[8];
#pragma unroll
        for (int r = 0; r < 8; r++) { tv[r] = -FLT_MAX; ti[r] = 0x7FFFFFFF; }
        for (int i = t; i < C; i += 32) {
            float v = s_cv[i]; int id = s_ci[i];
            if (lexgt(v, id, tv[7], ti[7])) {
                tv[7] = v; ti[7] = id;
#pragma unroll
                for (int p = 7; p > 0; p--) {
                    if (lexgt(tv[p], ti[p], tv[p - 1], ti[p - 1])) {
                        float fv = tv[p]; tv[p] = tv[p - 1]; tv[p - 1] = fv;
                        int   fi = ti[p]; ti[p] = ti[p - 1]; ti[p - 1] = fi;
                    }
                }
            }
        }
#pragma unroll
        for (int s = 1; s < 32; s <<= 1) {
            float pv[8]; int pi[8];
#pragma unroll
            for (int r = 0; r < 8; r++) {
                pv[r] = __shfl_xor_sync(0xffffffffu, tv[r], s);
                pi[r] = __shfl_xor_sync(0xffffffffu, ti[r], s);
            }
            float L[8]; int Li[8];
#pragma unroll
            for (int r = 0; r < 8; r++) {
                bool p = lexgt(tv[r], ti[r], pv[7 - r], pi[7 - r]);
                L[r]  = p ? tv[r] : pv[7 - r];
                Li[r] = p ? ti[r] : pi[7 - r];
            }
#define LCE(i, j)                                                   \
            {                                                       \
                if (lexgt(L[j], Li[j], L[i], Li[i])) {              \
                    float fv = L[i]; L[i] = L[j]; L[j] = fv;        \
                    int   fi = Li[i]; Li[i] = Li[j]; Li[j] = fi;    \
                }                                                   \
            }
            LCE(0, 4) LCE(1, 5) LCE(2, 6) LCE(3, 7)
            LCE(0, 2) LCE(1, 3) LCE(4, 6) LCE(5, 7)
            LCE(0, 1) LCE(2, 3) LCE(4, 5) LCE(6, 7)
#undef LCE
#pragma unroll
            for (int r = 0; r < 8; r++) { tv[r] = L[r]; ti[r] = Li[r]; }
        }
        // All lanes hold the identical value-descending top-8.
        if (t == 0) {
#pragma unroll
            for (int r = 0; r < 8; r++) g_idx[(size_t)n * 8 + r] = ti[r];
        }
    } else {
        // Overflow fallback: exact serial scan (never taken on this data).
        if (t == 0) {
            float tv[8]; int ti[8];
#pragma unroll
            for (int r = 0; r < 8; r++) { tv[r] = -FLT_MAX; ti[r] = 0x7FFFFFFF; }
            const float* xrow = x + (size_t)n * QD;
            for (int i = 0; i < QD; i++) {
                float v = xrow[i];
                if (lexgt(v, i, tv[7], ti[7])) {
                    tv[7] = v; ti[7] = i;
#pragma unroll
                    for (int p = 7; p > 0; p--) {
                        if (lexgt(tv[p], ti[p], tv[p - 1], ti[p - 1])) {
                            float fv = tv[p]; tv[p] = tv[p - 1]; tv[p - 1] = fv;
                            int   fi = ti[p]; ti[p] = ti[p - 1]; ti[p - 1] = fi;
                        }
                    }
                }
            }
#pragma unroll
            for (int r = 0; r < 8; r++) g_idx[(size_t)n * 8 + r] = ti[r];
        }
    }
}

// ---------------------------------------------------------------------------
// Kernel 3: tiled transpose weight[ED, QD] -> g_wT[QD, ED].
// Launched after the big x stream so wT stays L2-resident for the gather.
// ---------------------------------------------------------------------------
__global__ void transpose_kernel(const float* __restrict__ w) {
    __shared__ float tile[32][33];
    int qx = blockIdx.x * 32 + threadIdx.x;
    int ey = blockIdx.y * 32 + threadIdx.y;
#pragma unroll
    for (int j = 0; j < 32; j += 8)
        tile[threadIdx.y + j][threadIdx.x] = w[(size_t)(ey + j) * QD + qx];
    __syncthreads();
    int ex = blockIdx.y * 32 + threadIdx.x;
    int qy = blockIdx.x * 32 + threadIdx.y;
#pragma unroll
    for (int j = 0; j < 32; j += 8)
        g_wT[(size_t)(qy + j) * ED + ex] = tile[threadIdx.x][threadIdx.y + j];
}

// ---------------------------------------------------------------------------
// Kernel 4: out[n, :] = sum_{r<8} wT[idx_r, :] in descending-value order
// (== jax's summation order). Coalesced float4, wT served from L2.
// ---------------------------------------------------------------------------
__global__ __launch_bounds__(128) void gather_kernel(float* __restrict__ out) {
    const int n = blockIdx.x;
    const int t = threadIdx.x;
    int idx[8];
#pragma unroll
    for (int r = 0; r < 8; r++) idx[r] = __ldg(&g_idx[(size_t)n * 8 + r]);

    const float4* wT4 = reinterpret_cast<const float4*>(g_wT);
    float4 acc = make_float4(0.f, 0.f, 0.f, 0.f);
#pragma unroll
    for (int r = 0; r < 8; r++) {
        float4 wv = __ldg(&wT4[(size_t)idx[r] * (ED / 4) + t]);
        acc.x += wv.x; acc.y += wv.y; acc.z += wv.z; acc.w += wv.w;
    }
    reinterpret_cast<float4*>(out)[(size_t)n * (ED / 4) + t] = acc;
}

// ---------------------------------------------------------------------------
extern "C" void kernel_launch(void* const* d_in, const int* in_sizes, int n_in,
                              void* d_out, int out_size) {
    const float* x = (const float*)d_in[0];   // [NT, QD] f32
    const float* w = (const float*)d_in[1];   // [ED, QD] f32
    float* out = (float*)d_out;               // [NT, ED] f32

    rowmax_kernel<<<NT, 256>>>(x);
    select_kernel<<<NT, 256>>>(x);
    transpose_kernel<<<dim3(QD / 32, ED / 32), dim3(32, 8)>>>(w);
    gather_kernel<<<NT, 128>>>(out);
}

// round 15
// speedup vs baseline: 1.3877x; 1.3674x over previous
#include <cuda_runtime.h>
#include <float.h>
#include <cstdint>

#define QD 8192   // QUANT_DIM
#define ED 512    // EMBED_DIM
#define NT 8192   // N_TOKENS
#define CAP 256   // candidate capacity (overflow -> exact serial fallback)

// Scratch: weight.T [QD, ED] = 16 MB. Static __device__ global (no alloc).
__device__ float g_wT[(size_t)QD * ED];

// ---------------------------------------------------------------------------
// Kernel 1: tiled transpose weight[ED, QD] -> g_wT[QD, ED]
// ---------------------------------------------------------------------------
__global__ void transpose_kernel(const float* __restrict__ w) {
    __shared__ float tile[32][33];
    int qx = blockIdx.x * 32 + threadIdx.x;
    int ey = blockIdx.y * 32 + threadIdx.y;
#pragma unroll
    for (int j = 0; j < 32; j += 8)
        tile[threadIdx.y + j][threadIdx.x] = w[(size_t)(ey + j) * QD + qx];
    __syncthreads();
    int ex = blockIdx.y * 32 + threadIdx.x;
    int qy = blockIdx.x * 32 + threadIdx.y;
#pragma unroll
    for (int j = 0; j < 32; j += 8)
        g_wT[(size_t)(qy + j) * ED + ex] = tile[threadIdx.x][threadIdx.y + j];
}

// Strict total order lex(value desc, index asc) — matches jax.lax.top_k ties.
__device__ __forceinline__ bool lexgt(float av, int ai, float bv, int bi) {
    return (av > bv) || (av == bv && ai < bi);
}

// ---------------------------------------------------------------------------
// Kernel 2: block-per-token, MINIMAL tail.
// Threshold T = min of the 8 warp maxima: the 8 warp maxima are 8 distinct
// elements >= T, so the 8th-largest element v8 >= T and every true top-8
// element passes v >= T. Expected #candidates ~13 for Gaussian rows.
// ---------------------------------------------------------------------------
__global__ __launch_bounds__(256, 6) void topk_gather_kernel(
    const float* __restrict__ x, float* __restrict__ out) {
    const int n    = blockIdx.x;
    const int t    = threadIdx.x;
    const int lane = t & 31;
    const int wrp  = t >> 5;

    __shared__ __align__(16) float s_wmax[8];
    __shared__ float s_cv[CAP];
    __shared__ int   s_ci[CAP];
    __shared__ int   s_cnt;
    __shared__ int   s_fin[8];

    if (t == 0) s_cnt = 0;

    // ---- Phase 1: front-batched 8x LDG.128, pure FMNMX reduction.
    // Default cache policy (NOT ldcs): the row stays L2-hot for the rescan.
    const float4* xr = reinterpret_cast<const float4*>(x + (size_t)n * QD);
    float4 v[8];
#pragma unroll
    for (int c = 0; c < 8; c++) v[c] = xr[c * 256 + t];

    float gmax[4];   // 4 groups of 8 elements (pairs of float4)
#pragma unroll
    for (int c = 0; c < 4; c++) {
        float4 a = v[2 * c], b = v[2 * c + 1];
        float m0 = fmaxf(fmaxf(a.x, a.y), fmaxf(a.z, a.w));
        float m1 = fmaxf(fmaxf(b.x, b.y), fmaxf(b.z, b.w));
        gmax[c] = fmaxf(m0, m1);
    }
    float tmax = fmaxf(fmaxf(gmax[0], gmax[1]), fmaxf(gmax[2], gmax[3]));

    // ---- Phase 2: warp max (5 shfl), then T = min of the 8 warp maxima.
    float wm = tmax;
#pragma unroll
    for (int s = 16; s > 0; s >>= 1)
        wm = fmaxf(wm, __shfl_xor_sync(0xffffffffu, wm, s));
    if (lane == 0) s_wmax[wrp] = wm;
    __syncthreads();                                   // barrier 1

    float4 w0 = reinterpret_cast<const float4*>(s_wmax)[0];
    float4 w1 = reinterpret_cast<const float4*>(s_wmax)[1];
    const float T = fminf(fminf(fminf(w0.x, w0.y), fminf(w0.z, w0.w)),
                          fminf(fminf(w1.x, w1.y), fminf(w1.z, w1.w)));

    // ---- Phase 3: rescan triggered groups (expected ~13 elements total),
    // reload 2 float4 per triggered group from L2.
    if (tmax >= T) {
#pragma unroll
        for (int c = 0; c < 4; c++) {
            if (gmax[c] >= T) {
                float4 a = __ldg(&xr[(2 * c) * 256 + t]);
                float4 b = __ldg(&xr[(2 * c + 1) * 256 + t]);
                int ia = 4 * ((2 * c) * 256 + t);
                int ib = 4 * ((2 * c + 1) * 256 + t);
                float va[8] = {a.x, a.y, a.z, a.w, b.x, b.y, b.z, b.w};
                int   id[8] = {ia, ia + 1, ia + 2, ia + 3,
                               ib, ib + 1, ib + 2, ib + 3};
#pragma unroll
                for (int j = 0; j < 8; j++) {
                    if (va[j] >= T) {
                        int pos = atomicAdd(&s_cnt, 1);
                        if (pos < CAP) { s_cv[pos] = va[j]; s_ci[pos] = id[j]; }
                    }
                }
            }
        }
    }
    __syncthreads();                                   // barrier 2

    const int C = s_cnt;  // >= 8 guaranteed (>= 8 elements >= T exist)
    if (C <= CAP) {
        // ---- Phase 4 (warp 0): 8 lex-argmax passes over the candidates.
        // Lane j owns entries i == j (mod 32) for BOTH select and mark, so
        // no intra-warp smem ordering is needed; shfl does the reduction.
        if (t < 32) {
#pragma unroll
            for (int r = 0; r < 8; r++) {
                float bv = -FLT_MAX; int bi = 0x7FFFFFFF;
                for (int i = lane; i < C; i += 32) {
                    float cv = s_cv[i]; int ci = s_ci[i];
                    if (lexgt(cv, ci, bv, bi)) { bv = cv; bi = ci; }
                }
#pragma unroll
                for (int s = 16; s > 0; s >>= 1) {
                    float ov = __shfl_xor_sync(0xffffffffu, bv, s);
                    int   oi = __shfl_xor_sync(0xffffffffu, bi, s);
                    if (lexgt(ov, oi, bv, bi)) { bv = ov; bi = oi; }
                }
                if (lane == 0) s_fin[r] = bi;
                for (int i = lane; i < C; i += 32)
                    if (s_ci[i] == bi) s_cv[i] = -FLT_MAX;   // remove winner
            }
        }
    } else {
        // Overflow fallback: exact serial scan (never taken on this data).
        if (t == 0) {
            float tv[8]; int ti[8];
#pragma unroll
            for (int r = 0; r < 8; r++) { tv[r] = -FLT_MAX; ti[r] = 0x7FFFFFFF; }
            const float* xrow = x + (size_t)n * QD;
            for (int i = 0; i < QD; i++) {
                float vv = xrow[i];
                if (lexgt(vv, i, tv[7], ti[7])) {
                    tv[7] = vv; ti[7] = i;
#pragma unroll
                    for (int p = 7; p > 0; p--) {
                        if (lexgt(tv[p], ti[p], tv[p - 1], ti[p - 1])) {
                            float fv = tv[p]; tv[p] = tv[p - 1]; tv[p - 1] = fv;
                            int   fi = ti[p]; ti[p] = ti[p - 1]; ti[p - 1] = fi;
                        }
                    }
                }
            }
#pragma unroll
            for (int r = 0; r < 8; r++) s_fin[r] = ti[r];
        }
    }
    __syncthreads();                                   // barrier 3

    // ---- Phase 5: out[n, :] = sum_{r<8} wT[idx_r, :] (coalesced float2),
    // descending-value order == jax's summation order.
    int idx[8];
#pragma unroll
    for (int r = 0; r < 8; r++) idx[r] = s_fin[r];

    const float2* wT2 = reinterpret_cast<const float2*>(g_wT);
    float2 acc = make_float2(0.f, 0.f);
#pragma unroll
    for (int r = 0; r < 8; r++) {
        float2 wv = wT2[(size_t)idx[r] * (ED / 2) + t];
        acc.x += wv.x;
        acc.y += wv.y;
    }
    reinterpret_cast<float2*>(out)[(size_t)n * (ED / 2) + t] = acc;
}

// ---------------------------------------------------------------------------
extern "C" void kernel_launch(void* const* d_in, const int* in_sizes, int n_in,
                              void* d_out, int out_size) {
    const float* x = (const float*)d_in[0];   // [NT, QD] f32
    const float* w = (const float*)d_in[1];   // [ED, QD] f32
    float* out = (float*)d_out;               // [NT, ED] f32

    transpose_kernel<<<dim3(QD / 32, ED / 32), dim3(32, 8)>>>(w);
    topk_gather_kernel<<<NT, 256>>>(x, out);
}